// round 1
// baseline (speedup 1.0000x reference)
#include <cuda_runtime.h>
#include <cstdint>

// ---------------------------------------------------------------------------
// TractBundle: out = concat( x_a @ (Wa*Ma)^T, x_b @ (Wb*Mb)^T, x_c @ (Wc*Mc)^T )
// Masks are 64/64/32-sparse per output row -> sparse gather formulation.
// ---------------------------------------------------------------------------

#define CHUNK 1024                  // src elements staged per pass
#define TOK_TILE 32                 // tokens per block (lanes = tokens)
#define NDST_BLK 512                // dst columns per block
#define DPW 16                      // dsts per warp (512 / 32 warps)
#define SMEM_FLOATS (CHUNK * 33)    // padded [src][token] tile
#define SMEM_BYTES (SMEM_FLOATS * 4)

// Compressed tables (built per launch by prep kernel; deterministic).
__device__ int2 g_tabA[1024 * 64];
__device__ int2 g_tabB[512 * 64];
__device__ int2 g_tabC[512 * 32];
__device__ int  g_splA[1024 * 5];
__device__ int  g_splB[512 * 5];
__device__ int  g_splC[512 * 5];

// ---------------------------------------------------------------------------
// Prep: one warp per dst row. Scan src ascending, compact nonzero-mask entries
// into (idx, w*m) pairs, record cumulative counts at each 1024-src boundary.
// ---------------------------------------------------------------------------
__global__ void prep_kernel(const float* __restrict__ W,
                            const float* __restrict__ M,
                            int2* __restrict__ tab,
                            int*  __restrict__ spl,
                            int src, int n_dst, int conn)
{
    int row  = (blockIdx.x * blockDim.x + threadIdx.x) >> 5;
    int lane = threadIdx.x & 31;
    if (row >= n_dst) return;

    const float* wr = W + (size_t)row * src;
    const float* mr = M + (size_t)row * src;
    int2* trow = tab + (size_t)row * conn;

    if (lane == 0) spl[row * 5] = 0;
    int cnt = 0;
    for (int s0 = 0; s0 < src; s0 += 32) {
        float mv = mr[s0 + lane];
        unsigned bits = __ballot_sync(0xffffffffu, mv != 0.0f);
        if (mv != 0.0f) {
            int pos = cnt + __popc(bits & ((1u << lane) - 1u));
            float wv = wr[s0 + lane] * mv;
            trow[pos] = make_int2(s0 + lane, __float_as_int(wv));
        }
        cnt += __popc(bits);
        int s_end = s0 + 32;
        if ((s_end & (CHUNK - 1)) == 0 && lane == 0)
            spl[row * 5 + (s_end >> 10)] = cnt;
    }
}

// ---------------------------------------------------------------------------
// Main gather kernel.
//   grid.x = token tiles (256), grid.y = dst-block within tract
//   block  = 1024 threads = 32 warps; lane = token within tile
// Staging: warp w stages token (tile*32+w): global reads fully coalesced,
//   SMEM stores stride-33 words -> conflict-free.
// Compute: warp owns dst (uniform), lanes gather xs[idx*33+lane]:
//   32 consecutive words -> conflict-free, full-crossbar LDS.
// ---------------------------------------------------------------------------
__global__ __launch_bounds__(1024, 1)
void tract_kernel(const float* __restrict__ x,
                  const int2*  __restrict__ tab,
                  const int*   __restrict__ spl,
                  float* __restrict__ out,
                  int src, int conn, int passes, int col_off)
{
    extern __shared__ float xs[];
    const int tid  = threadIdx.x;
    const int lane = tid & 31;
    const int wid  = tid >> 5;
    const int token0   = blockIdx.x * TOK_TILE;
    const int dst_base = blockIdx.y * NDST_BLK;

    float acc[DPW];
#pragma unroll
    for (int d = 0; d < DPW; d++) acc[d] = 0.0f;

    for (int p = 0; p < passes; p++) {
        __syncthreads();
        // ---- stage x chunk: token (token0+wid), src [p*CHUNK, p*CHUNK+CHUNK)
        {
            const float* xrow = x + (size_t)(token0 + wid) * src + (size_t)p * CHUNK;
#pragma unroll
            for (int s0 = 0; s0 < CHUNK; s0 += 32)
                xs[(s0 + lane) * 33 + wid] = xrow[s0 + lane];
        }
        __syncthreads();

        const int pbase = p * CHUNK;
#pragma unroll
        for (int d = 0; d < DPW; d++) {
            const int dst = dst_base + wid * DPW + d;
            const int e0 = spl[dst * 5 + p];
            const int e1 = spl[dst * 5 + p + 1];
            const int2* t = tab + (size_t)dst * conn;
            float a0 = 0.0f, a1 = 0.0f;
            int e = e0;
            for (; e + 1 < e1; e += 2) {
                int2 ea = t[e];
                int2 eb = t[e + 1];
                a0 = fmaf(__int_as_float(ea.y), xs[(ea.x - pbase) * 33 + lane], a0);
                a1 = fmaf(__int_as_float(eb.y), xs[(eb.x - pbase) * 33 + lane], a1);
            }
            if (e < e1) {
                int2 ea = t[e];
                a0 = fmaf(__int_as_float(ea.y), xs[(ea.x - pbase) * 33 + lane], a0);
            }
            acc[d] += a0 + a1;
        }
    }

    // ---- transpose through SMEM, then coalesced global store
    __syncthreads();
#pragma unroll
    for (int d = 0; d < DPW; d++) {
        int dl = wid * DPW + d;            // local dst 0..511
        xs[dl * 33 + lane] = acc[d];
    }
    __syncthreads();

    const int total = TOK_TILE * NDST_BLK; // 16384
    for (int i = tid; i < total; i += 1024) {
        int t = i >> 9;                    // token within tile
        int c = i & (NDST_BLK - 1);        // local dst
        out[(size_t)(token0 + t) * 2048 + col_off + dst_base + c] = xs[c * 33 + t];
    }
}

// ---------------------------------------------------------------------------
// Launch
// ---------------------------------------------------------------------------
extern "C" void kernel_launch(void* const* d_in, const int* in_sizes, int n_in,
                              void* d_out, int out_size)
{
    // Layout detection: dict order (x_a,w_a,m_a,x_b,...) vs signature order
    // (x_a,x_b,x_c,w_a,w_b,w_c,m_a,m_b,m_c). w/m swap is harmless (w*m symmetric).
    const float *xa, *wa, *ma, *xb, *wb, *mb, *xc, *wc, *mc;
    if (in_sizes[1] == 1024 * 4096) {           // dict order
        xa = (const float*)d_in[0]; wa = (const float*)d_in[1]; ma = (const float*)d_in[2];
        xb = (const float*)d_in[3]; wb = (const float*)d_in[4]; mb = (const float*)d_in[5];
        xc = (const float*)d_in[6]; wc = (const float*)d_in[7]; mc = (const float*)d_in[8];
    } else {                                    // signature order
        xa = (const float*)d_in[0]; xb = (const float*)d_in[1]; xc = (const float*)d_in[2];
        wa = (const float*)d_in[3]; wb = (const float*)d_in[4]; wc = (const float*)d_in[5];
        ma = (const float*)d_in[6]; mb = (const float*)d_in[7]; mc = (const float*)d_in[8];
    }
    float* out = (float*)d_out;

    int2 *tabA, *tabB, *tabC;
    int  *splA, *splB, *splC;
    cudaGetSymbolAddress((void**)&tabA, g_tabA);
    cudaGetSymbolAddress((void**)&tabB, g_tabB);
    cudaGetSymbolAddress((void**)&tabC, g_tabC);
    cudaGetSymbolAddress((void**)&splA, g_splA);
    cudaGetSymbolAddress((void**)&splB, g_splB);
    cudaGetSymbolAddress((void**)&splC, g_splC);

    cudaFuncSetAttribute(tract_kernel, cudaFuncAttributeMaxDynamicSharedMemorySize,
                         SMEM_BYTES);

    // ---- prep: compress masks into (idx, w) tables
    prep_kernel<<<(1024 * 32 + 255) / 256, 256>>>(wa, ma, tabA, splA, 4096, 1024, 64);
    prep_kernel<<<( 512 * 32 + 255) / 256, 256>>>(wb, mb, tabB, splB, 4096,  512, 64);
    prep_kernel<<<( 512 * 32 + 255) / 256, 256>>>(wc, mc, tabC, splC, 2048,  512, 32);

    // ---- sparse gather GEMMs (8192 tokens / 32 per tile = 256 tiles)
    dim3 gridA(256, 2);  // 1024 dsts -> two 512-dst blocks
    dim3 gridB(256, 1);
    dim3 gridC(256, 1);
    tract_kernel<<<gridA, 1024, SMEM_BYTES>>>(xa, tabA, splA, out, 4096, 64, 4,    0);
    tract_kernel<<<gridB, 1024, SMEM_BYTES>>>(xb, tabB, splB, out, 4096, 64, 4, 1024);
    tract_kernel<<<gridC, 1024, SMEM_BYTES>>>(xc, tabC, splC, out, 2048, 32, 2, 1536);
}

// round 2
// speedup vs baseline: 1.3687x; 1.3687x over previous
#include <cuda_runtime.h>
#include <cstdint>

// ---------------------------------------------------------------------------
// TractBundle: out = concat( x_a @ (Wa*Ma)^T, x_b @ (Wb*Mb)^T, x_c @ (Wc*Mc)^T )
// Masks: 64/64/32-sparse per output row -> compressed sparse-gather formulation.
// Fused single kernel, float2 token pairs, precomputed smem offsets.
// ---------------------------------------------------------------------------

#define CHUNK 512                   // src elements staged per pass
#define S     66                    // smem row stride in floats (padded)
#define TOKS  64                    // tokens per block (2 per lane)
#define NDST  512                   // dst columns per block
#define DPW   16                    // dsts per warp
#define SMEM_WORDS (CHUNK * S)      // 33792
#define SMEM_BYTES (SMEM_WORDS * 4) // 135168

// Compressed tables: entry = ( (src_idx & 511)*66 , bits(w*m) ), 16B aligned
// for int4 paired loads. Splits stored transposed: spl[p * n_dst + dst].
__device__ __align__(16) int2 g_tabA[1024 * 64];
__device__ __align__(16) int2 g_tabB[512 * 64];
__device__ __align__(16) int2 g_tabC[512 * 32];
__device__ int g_splA[9 * 1024];
__device__ int g_splB[9 * 512];
__device__ int g_splC[5 * 512];

// ---------------------------------------------------------------------------
// Prep: one warp per dst row. Compact nonzero-mask entries (ascending src) into
// (smem_word_off, w*m) pairs; cumulative counts at each 512-src boundary.
// ---------------------------------------------------------------------------
__global__ void prep_kernel(const float* __restrict__ W,
                            const float* __restrict__ M,
                            int2* __restrict__ tab,
                            int*  __restrict__ spl,
                            int src, int n_dst, int conn)
{
    int row  = (blockIdx.x * blockDim.x + threadIdx.x) >> 5;
    int lane = threadIdx.x & 31;
    if (row >= n_dst) return;

    const float* wr = W + (size_t)row * src;
    const float* mr = M + (size_t)row * src;
    int2* trow = tab + (size_t)row * conn;

    if (lane == 0) spl[row] = 0;            // p = 0
    int cnt = 0;
    for (int s0 = 0; s0 < src; s0 += 32) {
        int s = s0 + lane;
        float mv = mr[s];
        unsigned bits = __ballot_sync(0xffffffffu, mv != 0.0f);
        if (mv != 0.0f) {
            int pos = cnt + __popc(bits & ((1u << lane) - 1u));
            trow[pos] = make_int2((s & (CHUNK - 1)) * S, __float_as_int(wr[s] * mv));
        }
        cnt += __popc(bits);
        int s_end = s0 + 32;
        if ((s_end & (CHUNK - 1)) == 0 && lane == 0)
            spl[(s_end >> 9) * n_dst + row] = cnt;
    }
}

// ---------------------------------------------------------------------------
// Fused gather kernel. 512 blocks:
//   [0,256)   tract A: tile = b>>1 (64-token tiles), dstblk = b&1
//   [256,384) tract B
//   [384,512) tract C
// Block = 1024 threads = 32 warps.
//   Staging: warp w owns tokens {2w, 2w+1}; lane = src offset.
//            STS.64 of token pair -> conflict-free.
//   Gather:  warp owns dst (uniform); lane owns token pair.
//            LDS.64 at (table_off + 2*lane) -> conflict-free, 2 MACs/access.
// ---------------------------------------------------------------------------
__global__ __launch_bounds__(1024, 1)
void tract_fused(const float* __restrict__ xa,
                 const float* __restrict__ xb,
                 const float* __restrict__ xc,
                 float* __restrict__ out)
{
    extern __shared__ float xs[];
    const int tid  = threadIdx.x;
    const int lane = tid & 31;
    const int wid  = tid >> 5;

    // ---- block -> (tract, tile, dst block) dispatch (all uniform) ----
    const float* x; const int2* tab; const int* spl;
    int src, conn, passes, n_dst, col_off, token0, dst_base;
    int b = blockIdx.x;
    if (b < 256) {
        x = xa; tab = g_tabA; spl = g_splA;
        src = 4096; conn = 64; passes = 8; n_dst = 1024;
        col_off = 0; token0 = (b >> 1) * TOKS; dst_base = (b & 1) * NDST;
    } else if (b < 384) {
        x = xb; tab = g_tabB; spl = g_splB;
        src = 4096; conn = 64; passes = 8; n_dst = 512;
        col_off = 1024; token0 = (b - 256) * TOKS; dst_base = 0;
    } else {
        x = xc; tab = g_tabC; spl = g_splC;
        src = 2048; conn = 32; passes = 4; n_dst = 512;
        col_off = 1536; token0 = (b - 384) * TOKS; dst_base = 0;
    }

    const int dstw = dst_base + wid * DPW;  // warp's first dst

    float2 acc[DPW];
#pragma unroll
    for (int d = 0; d < DPW; d++) acc[d] = make_float2(0.0f, 0.0f);

    int e_cur = 0;                          // lane (d&15)'s segment start

    for (int p = 0; p < passes; p++) {
        // prefetch this pass's segment ends (coalesced, latency hidden by staging)
        int e_nxt = spl[(p + 1) * n_dst + dstw + (lane & 15)];

        __syncthreads();                    // previous gather done before overwrite
        // ---- stage x chunk: warp w -> tokens {2w, 2w+1}, lane -> src ----
        {
            const float* xr0 = x + (size_t)(token0 + 2 * wid) * src + (size_t)p * CHUNK;
            const float* xr1 = xr0 + src;
#pragma unroll
            for (int s0 = 0; s0 < CHUNK; s0 += 32) {
                float v0 = xr0[s0 + lane];
                float v1 = xr1[s0 + lane];
                *(float2*)&xs[(s0 + lane) * S + 2 * wid] = make_float2(v0, v1);
            }
        }
        __syncthreads();

        // ---- gather: warp-uniform dst, lane = token pair ----
#pragma unroll
        for (int d = 0; d < DPW; d++) {
            int e0 = __shfl_sync(0xffffffffu, e_cur, d);
            int e1 = __shfl_sync(0xffffffffu, e_nxt, d);
            const int2* t = tab + (size_t)(dstw + d) * conn;
            float2 a = acc[d];
            int e = e0;
            if ((e & 1) && e < e1) {        // align to int4
                int2 q = t[e++];
                float2 xv = *(const float2*)&xs[q.x + 2 * lane];
                float w = __int_as_float(q.y);
                a.x = fmaf(w, xv.x, a.x);
                a.y = fmaf(w, xv.y, a.y);
            }
#pragma unroll 2
            for (; e + 1 < e1; e += 2) {
                int4 q = *(const int4*)&t[e];
                float2 xv0 = *(const float2*)&xs[q.x + 2 * lane];
                float2 xv1 = *(const float2*)&xs[q.z + 2 * lane];
                float w0 = __int_as_float(q.y);
                float w1 = __int_as_float(q.w);
                a.x = fmaf(w0, xv0.x, a.x);
                a.y = fmaf(w0, xv0.y, a.y);
                a.x = fmaf(w1, xv1.x, a.x);
                a.y = fmaf(w1, xv1.y, a.y);
            }
            if (e < e1) {
                int2 q = t[e];
                float2 xv = *(const float2*)&xs[q.x + 2 * lane];
                float w = __int_as_float(q.y);
                a.x = fmaf(w, xv.x, a.x);
                a.y = fmaf(w, xv.y, a.y);
            }
            acc[d] = a;
        }
        e_cur = e_nxt;
    }

    // ---- transpose through SMEM (conflict-free STS.64), coalesced store ----
    __syncthreads();
#pragma unroll
    for (int d = 0; d < DPW; d++) {
        int dl = wid * DPW + d;             // local dst 0..511
        *(float2*)&xs[dl * S + 2 * lane] = acc[d];
    }
    __syncthreads();

    const int total = NDST * TOKS;          // 32768
    for (int i = tid; i < total; i += 1024) {
        int t = i >> 9;                     // token within tile (0..63)
        int c = i & (NDST - 1);             // local dst
        out[(size_t)(token0 + t) * 2048 + col_off + dst_base + c] = xs[c * S + t];
    }
}

// ---------------------------------------------------------------------------
// Launch
// ---------------------------------------------------------------------------
extern "C" void kernel_launch(void* const* d_in, const int* in_sizes, int n_in,
                              void* d_out, int out_size)
{
    // Layout detection: dict order (x_a,w_a,m_a,...) vs signature order
    // (x_a,x_b,x_c,w_a,...). w/m swap is harmless (w*m symmetric).
    const float *xa, *wa, *ma, *xb, *wb, *mb, *xc, *wc, *mc;
    if (in_sizes[1] == 1024 * 4096) {           // dict order
        xa = (const float*)d_in[0]; wa = (const float*)d_in[1]; ma = (const float*)d_in[2];
        xb = (const float*)d_in[3]; wb = (const float*)d_in[4]; mb = (const float*)d_in[5];
        xc = (const float*)d_in[6]; wc = (const float*)d_in[7]; mc = (const float*)d_in[8];
    } else {                                    // signature order
        xa = (const float*)d_in[0]; xb = (const float*)d_in[1]; xc = (const float*)d_in[2];
        wa = (const float*)d_in[3]; wb = (const float*)d_in[4]; wc = (const float*)d_in[5];
        ma = (const float*)d_in[6]; mb = (const float*)d_in[7]; mc = (const float*)d_in[8];
    }
    float* out = (float*)d_out;

    int2 *tabA, *tabB, *tabC;
    int  *splA, *splB, *splC;
    cudaGetSymbolAddress((void**)&tabA, g_tabA);
    cudaGetSymbolAddress((void**)&tabB, g_tabB);
    cudaGetSymbolAddress((void**)&tabC, g_tabC);
    cudaGetSymbolAddress((void**)&splA, g_splA);
    cudaGetSymbolAddress((void**)&splB, g_splB);
    cudaGetSymbolAddress((void**)&splC, g_splC);

    cudaFuncSetAttribute(tract_fused, cudaFuncAttributeMaxDynamicSharedMemorySize,
                         SMEM_BYTES);

    // ---- prep: compress masks into (offset, w) tables ----
    prep_kernel<<<(1024 * 32 + 255) / 256, 256>>>(wa, ma, tabA, splA, 4096, 1024, 64);
    prep_kernel<<<( 512 * 32 + 255) / 256, 256>>>(wb, mb, tabB, splB, 4096,  512, 64);
    prep_kernel<<<( 512 * 32 + 255) / 256, 256>>>(wc, mc, tabC, splC, 2048,  512, 32);

    // ---- fused sparse gather for all three tracts ----
    tract_fused<<<512, 1024, SMEM_BYTES>>>(xa, xb, xc, out);
}